// round 11
// baseline (speedup 1.0000x reference)
#include <cuda_runtime.h>
#include <cstdint>

// Problem constants
#define HEADS 8
#define BATCH 8
#define SEQ   1024          // 32*32
#define HD    64
#define DMODEL 512
#define CIN   512
#define NB    (HEADS*BATCH) // 64 head-batches
#define HSTRIDE (BATCH*SEQ*HD) // 524288
#define QSCALE (0.125f * 1.4426950408889634f)   // 1/sqrt(64) * log2(e)

// Scratch (all values tf32-rounded by proj epilogue):
// g_Q: [n][s][pc(hd)]   (pre-scaled by QSCALE)
// g_K: [n][s][pc(hd)]
// g_V: [n][hd][ps(s)]   (transposed per head-batch)
__device__ float g_Q[NB * SEQ * HD];
__device__ float g_K[NB * SEQ * HD];
__device__ float g_V[NB * SEQ * HD];

// ---- helpers -------------------------------------------------------------
__device__ __forceinline__ uint32_t tf32bits(float x) {
    uint32_t u; asm("cvt.rna.tf32.f32 %0, %1;" : "=r"(u) : "f"(x)); return u;
}
__device__ __forceinline__ float tf32f(float x) {
    return __uint_as_float(tf32bits(x));
}
__device__ __forceinline__ float ex2(float x) {
    float r; asm("ex2.approx.ftz.f32 %0, %1;" : "=f"(r) : "f"(x)); return r;
}
__device__ __forceinline__ void mma8(float* d, const uint32_t* a, uint32_t b0, uint32_t b1) {
    asm volatile(
        "mma.sync.aligned.m16n8k8.row.col.f32.tf32.tf32.f32 "
        "{%0,%1,%2,%3}, {%4,%5,%6,%7}, {%8,%9}, {%0,%1,%2,%3};\n"
        : "+f"(d[0]), "+f"(d[1]), "+f"(d[2]), "+f"(d[3])
        : "r"(a[0]), "r"(a[1]), "r"(a[2]), "r"(a[3]), "r"(b0), "r"(b1));
}
__device__ __forceinline__ uint32_t fbits(float x) { return __float_as_uint(x); }
__device__ __forceinline__ void cpa16(uint32_t dst, const void* src) {
    asm volatile("cp.async.ca.shared.global [%0], [%1], 16;\n" :: "r"(dst), "l"(src));
}

// ---------------------------------------------------------------------------
// Kernel A: fused Q/K/V projection GEMM, tf32 MMA.
// 1 CTA/SM (141 KB smem): K-chunk 64, double-buffered cp.async of RAW fp32;
// tf32 cvt at fragment load (issue headroom exists at 1 warp/SMSP).
// A smem [128][68] ([m][k]); B smem [64][140] ([k][n]); both conflict-free.
// grid = (4, 64, 3).
// ---------------------------------------------------------------------------
#define AST 68
#define BST 140
#define ABUF (128 * AST)
#define BBUF (64 * BST)
#define PROJ_SMEM ((2 * ABUF + 2 * BBUF) * 4)   // 141312 B

__global__ void __launch_bounds__(128, 1) proj_kernel(
    const float* __restrict__ Xq, const float* __restrict__ Xk, const float* __restrict__ Xv,
    const float* __restrict__ Wq, const float* __restrict__ Wk, const float* __restrict__ Wv,
    const float* __restrict__ bq, const float* __restrict__ bk, const float* __restrict__ bv)
{
    extern __shared__ float psm[];
    float* As = psm;               // [2][128*AST]
    float* Bs = psm + 2 * ABUF;    // [2][64*BST]

    const int z = blockIdx.z;
    const float* __restrict__ X    = (z == 0) ? Xq : (z == 1) ? Xk : Xv;
    const float* __restrict__ W    = (z == 0) ? Wq : (z == 1) ? Wk : Wv;
    const float* __restrict__ bias = (z == 0) ? bq : (z == 1) ? bk : bv;
    float* __restrict__ Out        = (z == 0) ? g_Q : (z == 1) ? g_K : g_V;

    const int m0 = blockIdx.y * 128;
    const int n0 = blockIdx.x * 128;
    const int tid = threadIdx.x;
    const int lane = tid & 31, warp = tid >> 5;
    const int wm = (warp & 1) * 64;
    const int wn = (warp >> 1) * 64;

    const uint32_t as_a = (uint32_t)__cvta_generic_to_shared(As);
    const uint32_t bs_a = (uint32_t)__cvta_generic_to_shared(Bs);
    const int brow = tid & 63, bhalf = (tid >> 6) * 64;

    // Stage chunk t (64 k-values) into buffer buf: A 32KB + B 32KB, raw fp32.
    #define P_ISSUE(t, buf) do {                                                   \
        uint32_t ad = as_a + (uint32_t)(((buf) * ABUF + tid * AST) * 4);           \
        const float* asrc = X + (size_t)(m0 + tid) * CIN + (t) * 64;               \
        _Pragma("unroll")                                                          \
        for (int j = 0; j < 16; j++) cpa16(ad + j * 16, asrc + j * 4);             \
        uint32_t bd = bs_a + (uint32_t)(((buf) * BBUF + brow * BST + bhalf) * 4);  \
        const float* bsrc = W + (size_t)((t) * 64 + brow) * DMODEL + n0 + bhalf;   \
        _Pragma("unroll")                                                          \
        for (int j = 0; j < 16; j++) cpa16(bd + j * 16, bsrc + j * 4);             \
        asm volatile("cp.async.commit_group;\n" ::: "memory");                     \
    } while (0)

    float c[4][8][4];
    #pragma unroll
    for (int mt = 0; mt < 4; mt++)
        #pragma unroll
        for (int nt = 0; nt < 8; nt++)
            #pragma unroll
            for (int i = 0; i < 4; i++) c[mt][nt][i] = 0.0f;

    P_ISSUE(0, 0);

    for (int t = 0; t < 8; t++) {
        if (t + 1 < 8) {
            P_ISSUE(t + 1, (t + 1) & 1);
            asm volatile("cp.async.wait_group 1;\n" ::: "memory");
        } else {
            asm volatile("cp.async.wait_group 0;\n" ::: "memory");
        }
        __syncthreads();
        const float* Af = As + (t & 1) * ABUF;
        const float* Bf = Bs + (t & 1) * BBUF;

        #pragma unroll
        for (int ks = 0; ks < 8; ks++) {
            uint32_t A[4][4];
            #pragma unroll
            for (int mt = 0; mt < 4; mt++) {
                const float* ap = Af + (wm + mt * 16 + (lane >> 2)) * AST + 8 * ks + (lane & 3);
                A[mt][0] = tf32bits(ap[0]);
                A[mt][2] = tf32bits(ap[4]);
                A[mt][1] = tf32bits(ap[8 * AST]);
                A[mt][3] = tf32bits(ap[8 * AST + 4]);
            }
            #pragma unroll
            for (int nt = 0; nt < 8; nt++) {
                uint32_t b0 = tf32bits(Bf[(8 * ks + (lane & 3)) * BST + wn + 8 * nt + (lane >> 2)]);
                uint32_t b1 = tf32bits(Bf[(8 * ks + 4 + (lane & 3)) * BST + wn + 8 * nt + (lane >> 2)]);
                #pragma unroll
                for (int mt = 0; mt < 4; mt++) mma8(c[mt][nt], A[mt], b0, b1);
            }
        }
        __syncthreads();
    }
    #undef P_ISSUE

    // Epilogue: bias + tf32 round + conditioned layout scatter
    #pragma unroll
    for (int mt = 0; mt < 4; mt++) {
        #pragma unroll
        for (int nt = 0; nt < 8; nt++) {
            const int d = n0 + wn + 8 * nt + 2 * (lane & 3);
            const float2 bb = *(const float2*)&bias[d];
            const int head = d >> 6;
            const int dh = d & 63;
            const int p0 = (dh & ~7) | ((dh & 3) << 1) | ((dh >> 2) & 1);
            const int dh1 = dh + 1;
            const int p1 = (dh1 & ~7) | ((dh1 & 3) << 1) | ((dh1 >> 2) & 1);
            #pragma unroll
            for (int rh = 0; rh < 2; rh++) {
                const int m = m0 + wm + 16 * mt + (lane >> 2) + 8 * rh;
                float v0 = c[mt][nt][2 * rh] + bb.x;
                float v1 = c[mt][nt][2 * rh + 1] + bb.y;
                if (z == 0) { v0 = tf32f(v0 * QSCALE); v1 = tf32f(v1 * QSCALE); }
                else        { v0 = tf32f(v0);          v1 = tf32f(v1); }
                if (z == 2) {
                    const int b = m >> 10, s = m & 1023;
                    const int ps = (s & ~7) | ((s & 3) << 1) | ((s >> 2) & 1);
                    float* base = Out + (size_t)head * HSTRIDE + (size_t)b * (SEQ * HD) + ps;
                    base[(size_t)dh * SEQ]  = v0;
                    base[(size_t)dh1 * SEQ] = v1;
                } else {
                    float* base = Out + (size_t)head * HSTRIDE + (size_t)m * HD;
                    base[p0] = v0;
                    base[p1] = v1;
                }
            }
        }
    }
}

// ---------------------------------------------------------------------------
// Kernel B: flash attention, tf32 MMA (R7 — best measured, unchanged).
// Block 128 thr / 4 warps, 128 queries (warp: 32 q, mt=2). No online max
// (scores bounded). 32-key KV tiles, double-buffered cp.async.ca.
// Q fragments in registers. K smem [32][72], V smem [64][40]. grid = (8, 64).
// ---------------------------------------------------------------------------
#define KSTR 72
#define VSTR 40

__global__ void __launch_bounds__(128, 2) attn_kernel(float* __restrict__ out)
{
    __shared__ float Ks[2][32 * KSTR];
    __shared__ float Vs[2][64 * VSTR];

    const int n = blockIdx.y;
    const int tid = threadIdx.x;
    const int lane = tid & 31, warp = tid >> 5;
    const int q0 = blockIdx.x * 128;

    const float* Kg = g_K + (size_t)n * SEQ * HD;
    const float* Vg = g_V + (size_t)n * SEQ * HD;   // [64][1024]

    uint32_t qA[2][8][4];
    {
        const float* Qg = g_Q + ((size_t)n * SEQ + q0 + warp * 32) * HD;
        #pragma unroll
        for (int mt = 0; mt < 2; mt++)
            #pragma unroll
            for (int ks = 0; ks < 8; ks++) {
                const float* p = Qg + (size_t)(mt * 16 + (lane >> 2)) * HD + 8 * ks + 2 * (lane & 3);
                float2 lo = *(const float2*)p;
                float2 hi = *(const float2*)(p + 8 * HD);
                qA[mt][ks][0] = fbits(lo.x); qA[mt][ks][2] = fbits(lo.y);
                qA[mt][ks][1] = fbits(hi.x); qA[mt][ks][3] = fbits(hi.y);
            }
    }

    float o[2][8][4];
    #pragma unroll
    for (int mt = 0; mt < 2; mt++)
        #pragma unroll
        for (int nt = 0; nt < 8; nt++)
            #pragma unroll
            for (int i = 0; i < 4; i++) o[mt][nt][i] = 0.0f;
    float lrow[4] = {0.0f, 0.0f, 0.0f, 0.0f};

    const int krow = tid >> 2, kcol = (tid & 3) * 16;
    const int vrow = tid >> 1, vcol = (tid & 1) * 16;
    const uint32_t ks_a = (uint32_t)__cvta_generic_to_shared(&Ks[0][0]);
    const uint32_t vs_a = (uint32_t)__cvta_generic_to_shared(&Vs[0][0]);

    #define ISSUE_TILE(kv, b) do {                                             \
        uint32_t kd = ks_a + (uint32_t)(((b) * 32 * KSTR + krow * KSTR + kcol) * 4); \
        const float* ksrc = Kg + (size_t)((kv) + krow) * HD + kcol;            \
        _Pragma("unroll")                                                      \
        for (int j = 0; j < 4; j++) cpa16(kd + j * 16, ksrc + j * 4);          \
        uint32_t vd = vs_a + (uint32_t)(((b) * 64 * VSTR + vrow * VSTR + vcol) * 4); \
        const float* vsrc = Vg + (size_t)vrow * SEQ + (kv) + vcol;             \
        _Pragma("unroll")                                                      \
        for (int j = 0; j < 4; j++) cpa16(vd + j * 16, vsrc + j * 4);          \
        asm volatile("cp.async.commit_group;\n" ::: "memory");                 \
    } while (0)

    ISSUE_TILE(0, 0);

    const int src0 = (lane & ~3) | ((lane >> 1) & 1);
    const int src2 = src0 | 2;
    const bool oddl = (lane & 1);

    for (int t = 0; t < 32; t++) {
        if (t + 1 < 32) {
            ISSUE_TILE((t + 1) * 32, (t + 1) & 1);
            asm volatile("cp.async.wait_group 1;\n" ::: "memory");
        } else {
            asm volatile("cp.async.wait_group 0;\n" ::: "memory");
        }
        __syncthreads();
        const float* Kb = &Ks[t & 1][0];
        const float* Vb = &Vs[t & 1][0];

        float s[2][4][4];
        #pragma unroll
        for (int mt = 0; mt < 2; mt++)
            #pragma unroll
            for (int nt = 0; nt < 4; nt++)
                #pragma unroll
                for (int i = 0; i < 4; i++) s[mt][nt][i] = 0.0f;

        #pragma unroll
        for (int ks = 0; ks < 8; ks++) {
            uint32_t b0[4], b1[4];
            #pragma unroll
            for (int nt = 0; nt < 4; nt++) {
                float2 kv2 = *(const float2*)&Kb[(8 * nt + (lane >> 2)) * KSTR + 8 * ks + 2 * (lane & 3)];
                b0[nt] = fbits(kv2.x); b1[nt] = fbits(kv2.y);
            }
            #pragma unroll
            for (int nt = 0; nt < 4; nt++) {
                mma8(s[0][nt], qA[0][ks], b0[nt], b1[nt]);
                mma8(s[1][nt], qA[1][ks], b0[nt], b1[nt]);
            }
        }

        #pragma unroll
        for (int mt = 0; mt < 2; mt++)
            #pragma unroll
            for (int nt = 0; nt < 4; nt++) {
                float p0 = ex2(s[mt][nt][0]);
                float p1 = ex2(s[mt][nt][1]);
                float p2 = ex2(s[mt][nt][2]);
                float p3 = ex2(s[mt][nt][3]);
                s[mt][nt][0] = p0; s[mt][nt][1] = p1;
                s[mt][nt][2] = p2; s[mt][nt][3] = p3;
                lrow[mt * 2 + 0] += p0 + p1;
                lrow[mt * 2 + 1] += p2 + p3;
            }

        #pragma unroll
        for (int kt = 0; kt < 4; kt++) {
            uint32_t A[2][4];
            #pragma unroll
            for (int mt = 0; mt < 2; mt++) {
                float v0 = __shfl_sync(0xffffffffu, s[mt][kt][0], src0);
                float v1 = __shfl_sync(0xffffffffu, s[mt][kt][1], src0);
                float w0 = __shfl_sync(0xffffffffu, s[mt][kt][0], src2);
                float w1 = __shfl_sync(0xffffffffu, s[mt][kt][1], src2);
                A[mt][0] = tf32bits(oddl ? v1 : v0);
                A[mt][2] = tf32bits(oddl ? w1 : w0);
                v0 = __shfl_sync(0xffffffffu, s[mt][kt][2], src0);
                v1 = __shfl_sync(0xffffffffu, s[mt][kt][3], src0);
                w0 = __shfl_sync(0xffffffffu, s[mt][kt][2], src2);
                w1 = __shfl_sync(0xffffffffu, s[mt][kt][3], src2);
                A[mt][1] = tf32bits(oddl ? v1 : v0);
                A[mt][3] = tf32bits(oddl ? w1 : w0);
            }
            #pragma unroll
            for (int nt = 0; nt < 8; nt++) {
                float2 vv = *(const float2*)&Vb[(8 * nt + (lane >> 2)) * VSTR + 8 * kt + 2 * (lane & 3)];
                uint32_t b0 = fbits(vv.x), b1 = fbits(vv.y);
                mma8(o[0][nt], A[0], b0, b1);
                mma8(o[1][nt], A[1], b0, b1);
            }
        }
        __syncthreads();
    }
    #undef ISSUE_TILE

    const int head = n >> 3, b = n & 7;
    #pragma unroll
    for (int sl = 0; sl < 4; sl++) {
        lrow[sl] += __shfl_xor_sync(0xffffffffu, lrow[sl], 1);
        lrow[sl] += __shfl_xor_sync(0xffffffffu, lrow[sl], 2);
    }
    #pragma unroll
    for (int mt = 0; mt < 2; mt++) {
        #pragma unroll
        for (int rh = 0; rh < 2; rh++) {
            const int q = q0 + warp * 32 + mt * 16 + (lane >> 2) + 8 * rh;
            const float inv = 1.0f / lrow[mt * 2 + rh];
            float* orow = out + ((size_t)(b * SEQ + q)) * DMODEL + head * HD;
            #pragma unroll
            for (int nt = 0; nt < 8; nt++) {
                const int cc = 8 * nt + 2 * (lane & 3);
                *(float2*)(orow + cc) =
                    make_float2(o[mt][nt][2 * rh] * inv, o[mt][nt][2 * rh + 1] * inv);
            }
        }
    }
}

extern "C" void kernel_launch(void* const* d_in, const int* in_sizes, int n_in,
                              void* d_out, int out_size)
{
    const float* q_in = (const float*)d_in[0];
    const float* k_in = (const float*)d_in[1];
    const float* v_in = (const float*)d_in[2];
    const float* Wq   = (const float*)d_in[3];
    const float* bq   = (const float*)d_in[4];
    const float* Wk   = (const float*)d_in[5];
    const float* bk   = (const float*)d_in[6];
    const float* Wv   = (const float*)d_in[7];
    const float* bv   = (const float*)d_in[8];
    float* out = (float*)d_out;

    cudaFuncSetAttribute(proj_kernel, cudaFuncAttributeMaxDynamicSharedMemorySize, PROJ_SMEM);
    dim3 gp(DMODEL / 128, (BATCH * SEQ) / 128, 3);   // (4, 64, 3)
    proj_kernel<<<gp, 128, PROJ_SMEM>>>(q_in, k_in, v_in, Wq, Wk, Wv, bq, bk, bv);

    dim3 ga(SEQ / 128, NB);                          // (8, 64)
    attn_kernel<<<ga, 128>>>(out);
}

// round 12
// speedup vs baseline: 1.2153x; 1.2153x over previous
#include <cuda_runtime.h>
#include <cstdint>

// Problem constants
#define HEADS 8
#define BATCH 8
#define SEQ   1024          // 32*32
#define HD    64
#define DMODEL 512
#define CIN   512
#define NB    (HEADS*BATCH) // 64 head-batches
#define HSTRIDE (BATCH*SEQ*HD) // 524288
#define QSCALE (0.125f * 1.4426950408889634f)   // 1/sqrt(64) * log2(e)

// Scratch (all values tf32-rounded by proj epilogue):
// g_Q: [n][s][pc(hd)]   (pre-scaled by QSCALE)
// g_K: [n][s][pc(hd)]
// g_V: [n][hd][ps(s)]   (transposed per head-batch)
// pc/ps interleave pairs (x, x+4) within groups of 8: x -> (x&~7)|((x&3)<<1)|((x>>2)&1)
__device__ float g_Q[NB * SEQ * HD];
__device__ float g_K[NB * SEQ * HD];
__device__ float g_V[NB * SEQ * HD];

// ---- helpers -------------------------------------------------------------
__device__ __forceinline__ uint32_t tf32bits(float x) {
    uint32_t u; asm("cvt.rna.tf32.f32 %0, %1;" : "=r"(u) : "f"(x)); return u;
}
__device__ __forceinline__ float tf32f(float x) {
    return __uint_as_float(tf32bits(x));
}
__device__ __forceinline__ float ex2(float x) {
    float r; asm("ex2.approx.ftz.f32 %0, %1;" : "=f"(r) : "f"(x)); return r;
}
__device__ __forceinline__ void mma8(float* d, const uint32_t* a, uint32_t b0, uint32_t b1) {
    asm volatile(
        "mma.sync.aligned.m16n8k8.row.col.f32.tf32.tf32.f32 "
        "{%0,%1,%2,%3}, {%4,%5,%6,%7}, {%8,%9}, {%0,%1,%2,%3};\n"
        : "+f"(d[0]), "+f"(d[1]), "+f"(d[2]), "+f"(d[3])
        : "r"(a[0]), "r"(a[1]), "r"(a[2]), "r"(a[3]), "r"(b0), "r"(b1));
}
__device__ __forceinline__ uint32_t fbits(float x) { return __float_as_uint(x); }
__device__ __forceinline__ void cpa16(uint32_t dst, const void* src) {
    asm volatile("cp.async.ca.shared.global [%0], [%1], 16;\n" :: "r"(dst), "l"(src));
}

// ---------------------------------------------------------------------------
// Kernel A: fused Q/K/V projection GEMM, tf32 MMA (R6 — best measured proj).
// Block 128x128 tile, 128 threads = 4 warps, warp tile 64x64, 2 CTAs/SM.
// Register double-buffering: next k-chunk LDGs overlap current compute;
// tf32 cvt at the reg->smem store (off the mma critical path).
// ---------------------------------------------------------------------------
#define ASTR 36
#define BSTR 136
__global__ void __launch_bounds__(128, 2) proj_kernel(
    const float* __restrict__ Xq, const float* __restrict__ Xk, const float* __restrict__ Xv,
    const float* __restrict__ Wq, const float* __restrict__ Wk, const float* __restrict__ Wv,
    const float* __restrict__ bq, const float* __restrict__ bk, const float* __restrict__ bv)
{
    __shared__ float As[128 * ASTR];
    __shared__ float Bs[32 * BSTR];

    const int z = blockIdx.z;
    const float* __restrict__ X    = (z == 0) ? Xq : (z == 1) ? Xk : Xv;
    const float* __restrict__ W    = (z == 0) ? Wq : (z == 1) ? Wk : Wv;
    const float* __restrict__ bias = (z == 0) ? bq : (z == 1) ? bk : bv;
    float* __restrict__ Out        = (z == 0) ? g_Q : (z == 1) ? g_K : g_V;

    const int m0 = blockIdx.y * 128;
    const int n0 = blockIdx.x * 128;
    const int tid = threadIdx.x;
    const int lane = tid & 31, warp = tid >> 5;
    const int wm = (warp & 1) * 64;
    const int wn = (warp >> 1) * 64;

    const float* asrc0 = X + (size_t)(m0 + tid) * CIN;
    const float* bsrc0 = W + (size_t)(tid >> 2) * DMODEL + n0 + (tid & 3) * 4;

    float4 ra[8], rb[8];
    #pragma unroll
    for (int j = 0; j < 8; j++) {
        ra[j] = *(const float4*)(asrc0 + 4 * j);
        rb[j] = *(const float4*)(bsrc0 + 16 * j);
    }

    float c[4][8][4];
    #pragma unroll
    for (int mt = 0; mt < 4; mt++)
        #pragma unroll
        for (int nt = 0; nt < 8; nt++)
            #pragma unroll
            for (int i = 0; i < 4; i++) c[mt][nt][i] = 0.0f;

    for (int t = 0; t < 16; t++) {
        __syncthreads();   // previous compute done before overwriting smem
        {
            float* dst = As + tid * ASTR;
            #pragma unroll
            for (int j = 0; j < 8; j++)
                *(float4*)(dst + 4 * j) =
                    make_float4(tf32f(ra[j].x), tf32f(ra[j].y), tf32f(ra[j].z), tf32f(ra[j].w));
            float* bdst = Bs + (tid >> 2) * BSTR + (tid & 3) * 4;
            #pragma unroll
            for (int j = 0; j < 8; j++)
                *(float4*)(bdst + 16 * j) =
                    make_float4(tf32f(rb[j].x), tf32f(rb[j].y), tf32f(rb[j].z), tf32f(rb[j].w));
        }
        __syncthreads();

        if (t + 1 < 16) {  // prefetch next chunk; latency overlaps compute below
            const float* an = asrc0 + (t + 1) * 32;
            const float* bn = bsrc0 + (size_t)(t + 1) * 32 * DMODEL;
            #pragma unroll
            for (int j = 0; j < 8; j++) {
                ra[j] = *(const float4*)(an + 4 * j);
                rb[j] = *(const float4*)(bn + 16 * j);
            }
        }

        #pragma unroll
        for (int ks = 0; ks < 4; ks++) {
            uint32_t A[4][4];
            #pragma unroll
            for (int mt = 0; mt < 4; mt++) {
                const float* ap = As + (wm + mt * 16 + (lane >> 2)) * ASTR + 8 * ks + (lane & 3);
                A[mt][0] = fbits(ap[0]);
                A[mt][2] = fbits(ap[4]);
                A[mt][1] = fbits(ap[8 * ASTR]);
                A[mt][3] = fbits(ap[8 * ASTR + 4]);
            }
            #pragma unroll
            for (int nt = 0; nt < 8; nt++) {
                uint32_t b0 = fbits(Bs[(8 * ks + (lane & 3)) * BSTR + wn + 8 * nt + (lane >> 2)]);
                uint32_t b1 = fbits(Bs[(8 * ks + 4 + (lane & 3)) * BSTR + wn + 8 * nt + (lane >> 2)]);
                #pragma unroll
                for (int mt = 0; mt < 4; mt++) mma8(c[mt][nt], A[mt], b0, b1);
            }
        }
    }

    // Epilogue: bias + tf32 round + conditioned layout scatter
    #pragma unroll
    for (int mt = 0; mt < 4; mt++) {
        #pragma unroll
        for (int nt = 0; nt < 8; nt++) {
            const int d = n0 + wn + 8 * nt + 2 * (lane & 3);
            const float2 bb = *(const float2*)&bias[d];
            const int head = d >> 6;
            const int dh = d & 63;
            const int p0 = (dh & ~7) | ((dh & 3) << 1) | ((dh >> 2) & 1);
            const int dh1 = dh + 1;
            const int p1 = (dh1 & ~7) | ((dh1 & 3) << 1) | ((dh1 >> 2) & 1);
            #pragma unroll
            for (int rh = 0; rh < 2; rh++) {
                const int m = m0 + wm + 16 * mt + (lane >> 2) + 8 * rh;
                float v0 = c[mt][nt][2 * rh] + bb.x;
                float v1 = c[mt][nt][2 * rh + 1] + bb.y;
                if (z == 0) { v0 = tf32f(v0 * QSCALE); v1 = tf32f(v1 * QSCALE); }
                else        { v0 = tf32f(v0);          v1 = tf32f(v1); }
                if (z == 2) {
                    const int b = m >> 10, s = m & 1023;
                    const int ps = (s & ~7) | ((s & 3) << 1) | ((s >> 2) & 1);
                    float* base = Out + (size_t)head * HSTRIDE + (size_t)b * (SEQ * HD) + ps;
                    base[(size_t)dh * SEQ]  = v0;
                    base[(size_t)dh1 * SEQ] = v1;
                } else {
                    float* base = Out + (size_t)head * HSTRIDE + (size_t)m * HD;
                    base[p0] = v0;
                    base[p1] = v1;
                }
            }
        }
    }
}

// ---------------------------------------------------------------------------
// Kernel B: flash attention, tf32 MMA (R7 — best measured attn, unchanged).
// Block 128 thr / 4 warps, 128 queries (warp: 32 q, mt=2). No online max
// (scores bounded). 32-key KV tiles, double-buffered cp.async.ca.
// Q fragments in registers. K smem [32][72], V smem [64][40]. grid = (8, 64).
// ---------------------------------------------------------------------------
#define KSTR 72
#define VSTR 40

__global__ void __launch_bounds__(128, 2) attn_kernel(float* __restrict__ out)
{
    __shared__ float Ks[2][32 * KSTR];
    __shared__ float Vs[2][64 * VSTR];

    const int n = blockIdx.y;
    const int tid = threadIdx.x;
    const int lane = tid & 31, warp = tid >> 5;
    const int q0 = blockIdx.x * 128;

    const float* Kg = g_K + (size_t)n * SEQ * HD;
    const float* Vg = g_V + (size_t)n * SEQ * HD;   // [64][1024]

    uint32_t qA[2][8][4];
    {
        const float* Qg = g_Q + ((size_t)n * SEQ + q0 + warp * 32) * HD;
        #pragma unroll
        for (int mt = 0; mt < 2; mt++)
            #pragma unroll
            for (int ks = 0; ks < 8; ks++) {
                const float* p = Qg + (size_t)(mt * 16 + (lane >> 2)) * HD + 8 * ks + 2 * (lane & 3);
                float2 lo = *(const float2*)p;
                float2 hi = *(const float2*)(p + 8 * HD);
                qA[mt][ks][0] = fbits(lo.x); qA[mt][ks][2] = fbits(lo.y);
                qA[mt][ks][1] = fbits(hi.x); qA[mt][ks][3] = fbits(hi.y);
            }
    }

    float o[2][8][4];
    #pragma unroll
    for (int mt = 0; mt < 2; mt++)
        #pragma unroll
        for (int nt = 0; nt < 8; nt++)
            #pragma unroll
            for (int i = 0; i < 4; i++) o[mt][nt][i] = 0.0f;
    float lrow[4] = {0.0f, 0.0f, 0.0f, 0.0f};

    const int krow = tid >> 2, kcol = (tid & 3) * 16;
    const int vrow = tid >> 1, vcol = (tid & 1) * 16;
    const uint32_t ks_a = (uint32_t)__cvta_generic_to_shared(&Ks[0][0]);
    const uint32_t vs_a = (uint32_t)__cvta_generic_to_shared(&Vs[0][0]);

    #define ISSUE_TILE(kv, b) do {                                             \
        uint32_t kd = ks_a + (uint32_t)(((b) * 32 * KSTR + krow * KSTR + kcol) * 4); \
        const float* ksrc = Kg + (size_t)((kv) + krow) * HD + kcol;            \
        _Pragma("unroll")                                                      \
        for (int j = 0; j < 4; j++) cpa16(kd + j * 16, ksrc + j * 4);          \
        uint32_t vd = vs_a + (uint32_t)(((b) * 64 * VSTR + vrow * VSTR + vcol) * 4); \
        const float* vsrc = Vg + (size_t)vrow * SEQ + (kv) + vcol;             \
        _Pragma("unroll")                                                      \
        for (int j = 0; j < 4; j++) cpa16(vd + j * 16, vsrc + j * 4);          \
        asm volatile("cp.async.commit_group;\n" ::: "memory");                 \
    } while (0)

    ISSUE_TILE(0, 0);

    const int src0 = (lane & ~3) | ((lane >> 1) & 1);
    const int src2 = src0 | 2;
    const bool oddl = (lane & 1);

    for (int t = 0; t < 32; t++) {
        if (t + 1 < 32) {
            ISSUE_TILE((t + 1) * 32, (t + 1) & 1);
            asm volatile("cp.async.wait_group 1;\n" ::: "memory");
        } else {
            asm volatile("cp.async.wait_group 0;\n" ::: "memory");
        }
        __syncthreads();
        const float* Kb = &Ks[t & 1][0];
        const float* Vb = &Vs[t & 1][0];

        float s[2][4][4];
        #pragma unroll
        for (int mt = 0; mt < 2; mt++)
            #pragma unroll
            for (int nt = 0; nt < 4; nt++)
                #pragma unroll
                for (int i = 0; i < 4; i++) s[mt][nt][i] = 0.0f;

        #pragma unroll
        for (int ks = 0; ks < 8; ks++) {
            uint32_t b0[4], b1[4];
            #pragma unroll
            for (int nt = 0; nt < 4; nt++) {
                float2 kv2 = *(const float2*)&Kb[(8 * nt + (lane >> 2)) * KSTR + 8 * ks + 2 * (lane & 3)];
                b0[nt] = fbits(kv2.x); b1[nt] = fbits(kv2.y);
            }
            #pragma unroll
            for (int nt = 0; nt < 4; nt++) {
                mma8(s[0][nt], qA[0][ks], b0[nt], b1[nt]);
                mma8(s[1][nt], qA[1][ks], b0[nt], b1[nt]);
            }
        }

        #pragma unroll
        for (int mt = 0; mt < 2; mt++)
            #pragma unroll
            for (int nt = 0; nt < 4; nt++) {
                float p0 = ex2(s[mt][nt][0]);
                float p1 = ex2(s[mt][nt][1]);
                float p2 = ex2(s[mt][nt][2]);
                float p3 = ex2(s[mt][nt][3]);
                s[mt][nt][0] = p0; s[mt][nt][1] = p1;
                s[mt][nt][2] = p2; s[mt][nt][3] = p3;
                lrow[mt * 2 + 0] += p0 + p1;
                lrow[mt * 2 + 1] += p2 + p3;
            }

        #pragma unroll
        for (int kt = 0; kt < 4; kt++) {
            uint32_t A[2][4];
            #pragma unroll
            for (int mt = 0; mt < 2; mt++) {
                float v0 = __shfl_sync(0xffffffffu, s[mt][kt][0], src0);
                float v1 = __shfl_sync(0xffffffffu, s[mt][kt][1], src0);
                float w0 = __shfl_sync(0xffffffffu, s[mt][kt][0], src2);
                float w1 = __shfl_sync(0xffffffffu, s[mt][kt][1], src2);
                A[mt][0] = tf32bits(oddl ? v1 : v0);
                A[mt][2] = tf32bits(oddl ? w1 : w0);
                v0 = __shfl_sync(0xffffffffu, s[mt][kt][2], src0);
                v1 = __shfl_sync(0xffffffffu, s[mt][kt][3], src0);
                w0 = __shfl_sync(0xffffffffu, s[mt][kt][2], src2);
                w1 = __shfl_sync(0xffffffffu, s[mt][kt][3], src2);
                A[mt][1] = tf32bits(oddl ? v1 : v0);
                A[mt][3] = tf32bits(oddl ? w1 : w0);
            }
            #pragma unroll
            for (int nt = 0; nt < 8; nt++) {
                float2 vv = *(const float2*)&Vb[(8 * nt + (lane >> 2)) * VSTR + 8 * kt + 2 * (lane & 3)];
                uint32_t b0 = fbits(vv.x), b1 = fbits(vv.y);
                mma8(o[0][nt], A[0], b0, b1);
                mma8(o[1][nt], A[1], b0, b1);
            }
        }
        __syncthreads();
    }
    #undef ISSUE_TILE

    const int head = n >> 3, b = n & 7;
    #pragma unroll
    for (int sl = 0; sl < 4; sl++) {
        lrow[sl] += __shfl_xor_sync(0xffffffffu, lrow[sl], 1);
        lrow[sl] += __shfl_xor_sync(0xffffffffu, lrow[sl], 2);
    }
    #pragma unroll
    for (int mt = 0; mt < 2; mt++) {
        #pragma unroll
        for (int rh = 0; rh < 2; rh++) {
            const int q = q0 + warp * 32 + mt * 16 + (lane >> 2) + 8 * rh;
            const float inv = 1.0f / lrow[mt * 2 + rh];
            float* orow = out + ((size_t)(b * SEQ + q)) * DMODEL + head * HD;
            #pragma unroll
            for (int nt = 0; nt < 8; nt++) {
                const int cc = 8 * nt + 2 * (lane & 3);
                *(float2*)(orow + cc) =
                    make_float2(o[mt][nt][2 * rh] * inv, o[mt][nt][2 * rh + 1] * inv);
            }
        }
    }
}

extern "C" void kernel_launch(void* const* d_in, const int* in_sizes, int n_in,
                              void* d_out, int out_size)
{
    const float* q_in = (const float*)d_in[0];
    const float* k_in = (const float*)d_in[1];
    const float* v_in = (const float*)d_in[2];
    const float* Wq   = (const float*)d_in[3];
    const float* bq   = (const float*)d_in[4];
    const float* Wk   = (const float*)d_in[5];
    const float* bk   = (const float*)d_in[6];
    const float* Wv   = (const float*)d_in[7];
    const float* bv   = (const float*)d_in[8];
    float* out = (float*)d_out;

    dim3 gp(DMODEL / 128, (BATCH * SEQ) / 128, 3);   // (4, 64, 3)
    proj_kernel<<<gp, 128>>>(q_in, k_in, v_in, Wq, Wk, Wv, bq, bk, bv);

    dim3 ga(SEQ / 128, NB);                          // (8, 64)
    attn_kernel<<<ga, 128>>>(out);
}

// round 13
// speedup vs baseline: 1.6636x; 1.3688x over previous
#include <cuda_runtime.h>
#include <cuda_fp16.h>
#include <cstdint>

// Problem constants
#define HEADS 8
#define BATCH 8
#define SEQ   1024          // 32*32
#define HD    64
#define DMODEL 512
#define CIN   512
#define NB    (HEADS*BATCH) // 64 head-batches
#define HSTRIDE (BATCH*SEQ*HD) // 524288 (elements)
#define QSCALE (0.125f * 1.4426950408889634f)   // 1/sqrt(64) * log2(e)

// perm16: within each 16-block, interleave pairs (2c,2c+1),(2c+8,2c+9) -> 4c..4c+3
// x -> ((x>>1)&3)*4 + ((x>>3)&1)*2 + (x&1)
#define PRM16(x) (((((x) >> 1) & 3) << 2) | ((((x) >> 3) & 1) << 1) | ((x) & 1))

// Scratch (fp16, written by proj epilogue):
// g_Q: [n][s][P(hd)]  (pre-scaled by QSCALE)   P = perm16 within 16-blocks
// g_K: [n][s][P(hd)]
// g_V: [n][hd][P(s)]  (transposed per head-batch)
__device__ __half g_Q[NB * SEQ * HD];
__device__ __half g_K[NB * SEQ * HD];
__device__ __half g_V[NB * SEQ * HD];

// ---- helpers -------------------------------------------------------------
__device__ __forceinline__ uint32_t tf32bits(float x) {
    uint32_t u; asm("cvt.rna.tf32.f32 %0, %1;" : "=r"(u) : "f"(x)); return u;
}
__device__ __forceinline__ float tf32f(float x) {
    return __uint_as_float(tf32bits(x));
}
__device__ __forceinline__ float ex2(float x) {
    float r; asm("ex2.approx.ftz.f32 %0, %1;" : "=f"(r) : "f"(x)); return r;
}
// tf32 m16n8k8 (proj)
__device__ __forceinline__ void mma8(float* d, const uint32_t* a, uint32_t b0, uint32_t b1) {
    asm volatile(
        "mma.sync.aligned.m16n8k8.row.col.f32.tf32.tf32.f32 "
        "{%0,%1,%2,%3}, {%4,%5,%6,%7}, {%8,%9}, {%0,%1,%2,%3};\n"
        : "+f"(d[0]), "+f"(d[1]), "+f"(d[2]), "+f"(d[3])
        : "r"(a[0]), "r"(a[1]), "r"(a[2]), "r"(a[3]), "r"(b0), "r"(b1));
}
// fp16 m16n8k16, fp32 accum (attn)
__device__ __forceinline__ void mma16(float* d, const uint32_t* a, uint32_t b0, uint32_t b1) {
    asm volatile(
        "mma.sync.aligned.m16n8k16.row.col.f32.f16.f16.f32 "
        "{%0,%1,%2,%3}, {%4,%5,%6,%7}, {%8,%9}, {%0,%1,%2,%3};\n"
        : "+f"(d[0]), "+f"(d[1]), "+f"(d[2]), "+f"(d[3])
        : "r"(a[0]), "r"(a[1]), "r"(a[2]), "r"(a[3]), "r"(b0), "r"(b1));
}
__device__ __forceinline__ uint32_t packh(float hi, float lo) {
    uint32_t r; asm("cvt.rn.f16x2.f32 %0, %1, %2;" : "=r"(r) : "f"(hi), "f"(lo)); return r;
}
__device__ __forceinline__ uint32_t fbits(float x) { return __float_as_uint(x); }
__device__ __forceinline__ void cpa16(uint32_t dst, const void* src) {
    asm volatile("cp.async.ca.shared.global [%0], [%1], 16;\n" :: "r"(dst), "l"(src));
}

// ---------------------------------------------------------------------------
// Kernel A: fused Q/K/V projection GEMM, tf32 MMA (R6 mainloop — best measured).
// Epilogue writes fp16 perm16 layouts above.
// ---------------------------------------------------------------------------
#define ASTR 36
#define BSTR 136
__global__ void __launch_bounds__(128, 2) proj_kernel(
    const float* __restrict__ Xq, const float* __restrict__ Xk, const float* __restrict__ Xv,
    const float* __restrict__ Wq, const float* __restrict__ Wk, const float* __restrict__ Wv,
    const float* __restrict__ bq, const float* __restrict__ bk, const float* __restrict__ bv)
{
    __shared__ float As[128 * ASTR];
    __shared__ float Bs[32 * BSTR];

    const int z = blockIdx.z;
    const float* __restrict__ X    = (z == 0) ? Xq : (z == 1) ? Xk : Xv;
    const float* __restrict__ W    = (z == 0) ? Wq : (z == 1) ? Wk : Wv;
    const float* __restrict__ bias = (z == 0) ? bq : (z == 1) ? bk : bv;
    __half* __restrict__ Out       = (z == 0) ? g_Q : (z == 1) ? g_K : g_V;

    const int m0 = blockIdx.y * 128;
    const int n0 = blockIdx.x * 128;
    const int tid = threadIdx.x;
    const int lane = tid & 31, warp = tid >> 5;
    const int wm = (warp & 1) * 64;
    const int wn = (warp >> 1) * 64;

    const float* asrc0 = X + (size_t)(m0 + tid) * CIN;
    const float* bsrc0 = W + (size_t)(tid >> 2) * DMODEL + n0 + (tid & 3) * 4;

    float4 ra[8], rb[8];
    #pragma unroll
    for (int j = 0; j < 8; j++) {
        ra[j] = *(const float4*)(asrc0 + 4 * j);
        rb[j] = *(const float4*)(bsrc0 + 16 * j);
    }

    float c[4][8][4];
    #pragma unroll
    for (int mt = 0; mt < 4; mt++)
        #pragma unroll
        for (int nt = 0; nt < 8; nt++)
            #pragma unroll
            for (int i = 0; i < 4; i++) c[mt][nt][i] = 0.0f;

    for (int t = 0; t < 16; t++) {
        __syncthreads();   // previous compute done before overwriting smem
        {
            float* dst = As + tid * ASTR;
            #pragma unroll
            for (int j = 0; j < 8; j++)
                *(float4*)(dst + 4 * j) =
                    make_float4(tf32f(ra[j].x), tf32f(ra[j].y), tf32f(ra[j].z), tf32f(ra[j].w));
            float* bdst = Bs + (tid >> 2) * BSTR + (tid & 3) * 4;
            #pragma unroll
            for (int j = 0; j < 8; j++)
                *(float4*)(bdst + 16 * j) =
                    make_float4(tf32f(rb[j].x), tf32f(rb[j].y), tf32f(rb[j].z), tf32f(rb[j].w));
        }
        __syncthreads();

        if (t + 1 < 16) {  // prefetch next chunk; latency overlaps compute below
            const float* an = asrc0 + (t + 1) * 32;
            const float* bn = bsrc0 + (size_t)(t + 1) * 32 * DMODEL;
            #pragma unroll
            for (int j = 0; j < 8; j++) {
                ra[j] = *(const float4*)(an + 4 * j);
                rb[j] = *(const float4*)(bn + 16 * j);
            }
        }

        #pragma unroll
        for (int ks = 0; ks < 4; ks++) {
            uint32_t A[4][4];
            #pragma unroll
            for (int mt = 0; mt < 4; mt++) {
                const float* ap = As + (wm + mt * 16 + (lane >> 2)) * ASTR + 8 * ks + (lane & 3);
                A[mt][0] = fbits(ap[0]);
                A[mt][2] = fbits(ap[4]);
                A[mt][1] = fbits(ap[8 * ASTR]);
                A[mt][3] = fbits(ap[8 * ASTR + 4]);
            }
            #pragma unroll
            for (int nt = 0; nt < 8; nt++) {
                uint32_t b0 = fbits(Bs[(8 * ks + (lane & 3)) * BSTR + wn + 8 * nt + (lane >> 2)]);
                uint32_t b1 = fbits(Bs[(8 * ks + 4 + (lane & 3)) * BSTR + wn + 8 * nt + (lane >> 2)]);
                #pragma unroll
                for (int mt = 0; mt < 4; mt++) mma8(c[mt][nt], A[mt], b0, b1);
            }
        }
    }

    // Epilogue: bias + fp16 round + perm16 layout scatter
    #pragma unroll
    for (int mt = 0; mt < 4; mt++) {
        #pragma unroll
        for (int nt = 0; nt < 8; nt++) {
            const int d = n0 + wn + 8 * nt + 2 * (lane & 3);
            const float2 bb = *(const float2*)&bias[d];
            const int head = d >> 6;
            const int dh = d & 63;                       // even
            const int pq = (dh & ~15) | PRM16(dh & 15);  // pair -> (pq, pq+1)
            #pragma unroll
            for (int rh = 0; rh < 2; rh++) {
                const int m = m0 + wm + 16 * mt + (lane >> 2) + 8 * rh;
                float v0 = c[mt][nt][2 * rh] + bb.x;
                float v1 = c[mt][nt][2 * rh + 1] + bb.y;
                if (z == 0) { v0 *= QSCALE; v1 *= QSCALE; }
                const __half h0 = __float2half_rn(v0);
                const __half h1 = __float2half_rn(v1);
                if (z == 2) {
                    const int b = m >> 10, s = m & 1023;
                    const int ps = (s & ~15) | PRM16(s & 15);
                    __half* base = Out + (size_t)head * HSTRIDE + (size_t)b * (SEQ * HD) + ps;
                    base[(size_t)dh * SEQ]       = h0;
                    base[(size_t)(dh + 1) * SEQ] = h1;
                } else {
                    __half* base = Out + (size_t)head * HSTRIDE + (size_t)m * HD + pq;
                    *(__half2*)base = __halves2half2(h0, h1);
                }
            }
        }
    }
}

// ---------------------------------------------------------------------------
// Kernel B: flash attention, fp16 MMA m16n8k16.
// Block 128 thr / 4 warps, 128 queries (warp: 32 q, mt=2). No online max.
// 32-key KV tiles, double-buffered cp.async.ca, fp16 smem (K [32][80],
// V [64][48] halves — conflict-free per half-warp). Q fragments in registers.
// P(C-frag) packs directly into PV A-frag — NO shuffles. grid = (8, 64).
// ---------------------------------------------------------------------------
#define KSTRh 80
#define VSTRh 48

__global__ void __launch_bounds__(128, 2) attn_kernel(float* __restrict__ out)
{
    __shared__ __half Ks[2][32 * KSTRh];   // 10240 B
    __shared__ __half Vs[2][64 * VSTRh];   // 12288 B

    const int n = blockIdx.y;
    const int tid = threadIdx.x;
    const int lane = tid & 31, warp = tid >> 5;
    const int q0 = blockIdx.x * 128;

    const __half* Kg = g_K + (size_t)n * SEQ * HD;
    const __half* Vg = g_V + (size_t)n * SEQ * HD;   // [64][1024]

    // ---- Q fragments in registers: a0/a1/a2/a3 per (mt, k16-step) ----
    uint32_t qA[2][4][4];
    {
        #pragma unroll
        for (int mt = 0; mt < 2; mt++) {
            const int row = q0 + warp * 32 + mt * 16 + (lane >> 2);
            const __half* rp = g_Q + ((size_t)n * SEQ + row) * HD;
            #pragma unroll
            for (int ks = 0; ks < 4; ks++) {
                uint2 lo = *(const uint2*)(rp + 16 * ks + 4 * (lane & 3));
                uint2 hi = *(const uint2*)(rp + 8 * HD + 16 * ks + 4 * (lane & 3));
                qA[mt][ks][0] = lo.x; qA[mt][ks][1] = hi.x;
                qA[mt][ks][2] = lo.y; qA[mt][ks][3] = hi.y;
            }
        }
    }

    float o[2][8][4];
    #pragma unroll
    for (int mt = 0; mt < 2; mt++)
        #pragma unroll
        for (int nt = 0; nt < 8; nt++)
            #pragma unroll
            for (int i = 0; i < 4; i++) o[mt][nt][i] = 0.0f;
    float lrow[4] = {0.0f, 0.0f, 0.0f, 0.0f};

    // cp.async staging: K tile 32 rows x 128B; V tile 64 rows x 64B
    const int krow = tid >> 2, kc = tid & 3;   // 4 thr/row, 32B each
    const int vrow = tid >> 1, vc = tid & 1;   // 2 thr/row, 32B each
    const uint32_t ks_a = (uint32_t)__cvta_generic_to_shared(&Ks[0][0]);
    const uint32_t vs_a = (uint32_t)__cvta_generic_to_shared(&Vs[0][0]);

    #define ISSUE_TILE(kv, b) do {                                                 \
        uint32_t kd = ks_a + (uint32_t)(((b) * 32 * KSTRh + krow * KSTRh) * 2 + kc * 32); \
        const __half* ksrc = Kg + (size_t)((kv) + krow) * HD + kc * 16;            \
        cpa16(kd, ksrc); cpa16(kd + 16, ksrc + 8);                                 \
        uint32_t vd = vs_a + (uint32_t)(((b) * 64 * VSTRh + vrow * VSTRh) * 2 + vc * 32); \
        const __half* vsrc = Vg + (size_t)vrow * SEQ + (kv) + vc * 16;             \
        cpa16(vd, vsrc); cpa16(vd + 16, vsrc + 8);                                 \
        asm volatile("cp.async.commit_group;\n" ::: "memory");                     \
    } while (0)

    ISSUE_TILE(0, 0);

    for (int t = 0; t < 32; t++) {
        if (t + 1 < 32) {
            ISSUE_TILE((t + 1) * 32, (t + 1) & 1);
            asm volatile("cp.async.wait_group 1;\n" ::: "memory");
        } else {
            asm volatile("cp.async.wait_group 0;\n" ::: "memory");
        }
        __syncthreads();
        const __half* Kb = &Ks[t & 1][0];
        const __half* Vb = &Vs[t & 1][0];

        // ---- S = Q * K^T (32 keys): 4 k16-steps x 4 n8-tiles x 2 mt ----
        float s[2][4][4];
        #pragma unroll
        for (int mt = 0; mt < 2; mt++)
            #pragma unroll
            for (int nt = 0; nt < 4; nt++)
                #pragma unroll
                for (int i = 0; i < 4; i++) s[mt][nt][i] = 0.0f;

        #pragma unroll
        for (int ks = 0; ks < 4; ks++) {
            #pragma unroll
            for (int nt = 0; nt < 4; nt++) {
                uint2 kv2 = *(const uint2*)&Kb[(8 * nt + (lane >> 2)) * KSTRh + 16 * ks + 4 * (lane & 3)];
                mma16(s[0][nt], qA[0][ks], kv2.x, kv2.y);
                mma16(s[1][nt], qA[1][ks], kv2.x, kv2.y);
            }
        }

        // ---- p = exp2(s); lane-local row sums (no max, no rescale) ----
        #pragma unroll
        for (int mt = 0; mt < 2; mt++)
            #pragma unroll
            for (int nt = 0; nt < 4; nt++) {
                float p0 = ex2(s[mt][nt][0]);
                float p1 = ex2(s[mt][nt][1]);
                float p2 = ex2(s[mt][nt][2]);
                float p3 = ex2(s[mt][nt][3]);
                s[mt][nt][0] = p0; s[mt][nt][1] = p1;
                s[mt][nt][2] = p2; s[mt][nt][3] = p3;
                lrow[mt * 2 + 0] += p0 + p1;
                lrow[mt * 2 + 1] += p2 + p3;
            }

        // ---- P: C-frag -> fp16 A-frag (direct pack, no shuffles) ----
        uint32_t pA[2][2][4];
        #pragma unroll
        for (int mt = 0; mt < 2; mt++)
            #pragma unroll
            for (int kt = 0; kt < 2; kt++) {
                pA[mt][kt][0] = packh(s[mt][2 * kt][1],     s[mt][2 * kt][0]);
                pA[mt][kt][1] = packh(s[mt][2 * kt][3],     s[mt][2 * kt][2]);
                pA[mt][kt][2] = packh(s[mt][2 * kt + 1][1], s[mt][2 * kt + 1][0]);
                pA[mt][kt][3] = packh(s[mt][2 * kt + 1][3], s[mt][2 * kt + 1][2]);
            }

        // ---- O += P * V: 2 k16-steps x 8 n8-tiles x 2 mt ----
        #pragma unroll
        for (int kt = 0; kt < 2; kt++) {
            #pragma unroll
            for (int nt = 0; nt < 8; nt++) {
                uint2 vv = *(const uint2*)&Vb[(8 * nt + (lane >> 2)) * VSTRh + 16 * kt + 4 * (lane & 3)];
                mma16(o[0][nt], pA[0][kt], vv.x, vv.y);
                mma16(o[1][nt], pA[1][kt], vv.x, vv.y);
            }
        }
        __syncthreads();
    }
    #undef ISSUE_TILE

    // Epilogue: one-time l reduction, normalize, head-major scatter
    const int head = n >> 3, b = n & 7;
    #pragma unroll
    for (int sl = 0; sl < 4; sl++) {
        lrow[sl] += __shfl_xor_sync(0xffffffffu, lrow[sl], 1);
        lrow[sl] += __shfl_xor_sync(0xffffffffu, lrow[sl], 2);
    }
    #pragma unroll
    for (int mt = 0; mt < 2; mt++) {
        #pragma unroll
        for (int rh = 0; rh < 2; rh++) {
            const int q = q0 + warp * 32 + mt * 16 + (lane >> 2) + 8 * rh;
            const float inv = 1.0f / lrow[mt * 2 + rh];
            float* orow = out + ((size_t)(b * SEQ + q)) * DMODEL + head * HD;
            #pragma unroll
            for (int nt = 0; nt < 8; nt++) {
                const int cc = 8 * nt + 2 * (lane & 3);
                *(float2*)(orow + cc) =
                    make_float2(o[mt][nt][2 * rh] * inv, o[mt][nt][2 * rh + 1] * inv);
            }
        }
    }
}

extern "C" void kernel_launch(void* const* d_in, const int* in_sizes, int n_in,
                              void* d_out, int out_size)
{
    const float* q_in = (const float*)d_in[0];
    const float* k_in = (const float*)d_in[1];
    const float* v_in = (const float*)d_in[2];
    const float* Wq   = (const float*)d_in[3];
    const float* bq   = (const float*)d_in[4];
    const float* Wk   = (const float*)d_in[5];
    const float* bk   = (const float*)d_in[6];
    const float* Wv   = (const float*)d_in[7];
    const float* bv   = (const float*)d_in[8];
    float* out = (float*)d_out;

    dim3 gp(DMODEL / 128, (BATCH * SEQ) / 128, 3);   // (4, 64, 3)
    proj_kernel<<<gp, 128>>>(q_in, k_in, v_in, Wq, Wk, Wv, bq, bk, bv);

    dim3 ga(SEQ / 128, NB);                          // (8, 64)
    attn_kernel<<<ga, 128>>>(out);
}

// round 14
// speedup vs baseline: 2.1857x; 1.3139x over previous
#include <cuda_runtime.h>
#include <cuda_fp16.h>
#include <cstdint>

// Problem constants
#define HEADS 8
#define BATCH 8
#define SEQ   1024          // 32*32
#define HD    64
#define DMODEL 512
#define CIN   512
#define NB    (HEADS*BATCH) // 64 head-batches
#define HSTRIDE (BATCH*SEQ*HD) // 524288 (elements)
#define QSCALE (0.125f * 1.4426950408889634f)   // 1/sqrt(64) * log2(e)

// perm16: within each 16-block, interleave pairs (2c,2c+1),(2c+8,2c+9) -> 4c..4c+3
#define PRM16(x) (((((x) >> 1) & 3) << 2) | ((((x) >> 3) & 1) << 1) | ((x) & 1))

// Scratch (fp16, written by proj epilogue):
// g_Q: [n][s][P(hd)]  (pre-scaled by QSCALE)   P = perm16 within 16-blocks
// g_K: [n][s][P(hd)]
// g_V: [n][hd][P(s)]  (transposed per head-batch)
__device__ __half g_Q[NB * SEQ * HD];
__device__ __half g_K[NB * SEQ * HD];
__device__ __half g_V[NB * SEQ * HD];

// ---- helpers -------------------------------------------------------------
__device__ __forceinline__ float ex2(float x) {
    float r; asm("ex2.approx.ftz.f32 %0, %1;" : "=f"(r) : "f"(x)); return r;
}
// fp16 m16n8k16, fp32 accum
__device__ __forceinline__ void mma16(float* d, const uint32_t* a, uint32_t b0, uint32_t b1) {
    asm volatile(
        "mma.sync.aligned.m16n8k16.row.col.f32.f16.f16.f32 "
        "{%0,%1,%2,%3}, {%4,%5,%6,%7}, {%8,%9}, {%0,%1,%2,%3};\n"
        : "+f"(d[0]), "+f"(d[1]), "+f"(d[2]), "+f"(d[3])
        : "r"(a[0]), "r"(a[1]), "r"(a[2]), "r"(a[3]), "r"(b0), "r"(b1));
}
__device__ __forceinline__ uint32_t packh(float hi, float lo) {
    uint32_t r; asm("cvt.rn.f16x2.f32 %0, %1, %2;" : "=r"(r) : "f"(hi), "f"(lo)); return r;
}
__device__ __forceinline__ void cpa16(uint32_t dst, const void* src) {
    asm volatile("cp.async.ca.shared.global [%0], [%1], 16;\n" :: "r"(dst), "l"(src));
}

// ---------------------------------------------------------------------------
// Kernel A: fused Q/K/V projection GEMM, fp16 MMA m16n8k16.
// Block 128x128 tile, 128 threads = 4 warps, warp tile 64x64, 2 CTAs/SM.
// R6 register-double-buffer skeleton; smem tiles fp16 perm16:
//   A [m=128][perm(k=32)] stride 48 halves; B [n=128][perm(k=32)] stride 48
// (B transposed at staging via 32 coalesced scalar LDGs per thread).
// Every fragment load is a single LDS.64; conflict-free (V-tile pattern).
// ---------------------------------------------------------------------------
#define AST 48
__global__ void __launch_bounds__(128, 2) proj_kernel(
    const float* __restrict__ Xq, const float* __restrict__ Xk, const float* __restrict__ Xv,
    const float* __restrict__ Wq, const float* __restrict__ Wk, const float* __restrict__ Wv,
    const float* __restrict__ bq, const float* __restrict__ bk, const float* __restrict__ bv)
{
    __shared__ __half As[128 * AST];   // 12288 B
    __shared__ __half Bs[128 * AST];   // 12288 B

    const int z = blockIdx.z;
    const float* __restrict__ X    = (z == 0) ? Xq : (z == 1) ? Xk : Xv;
    const float* __restrict__ W    = (z == 0) ? Wq : (z == 1) ? Wk : Wv;
    const float* __restrict__ bias = (z == 0) ? bq : (z == 1) ? bk : bv;
    __half* __restrict__ Out       = (z == 0) ? g_Q : (z == 1) ? g_K : g_V;

    const int m0 = blockIdx.y * 128;
    const int n0 = blockIdx.x * 128;
    const int tid = threadIdx.x;
    const int lane = tid & 31, warp = tid >> 5;
    const int wm = (warp & 1) * 64;
    const int wn = (warp >> 1) * 64;

    const float* asrc0 = X + (size_t)(m0 + tid) * CIN;   // thread = A row
    const float* wsrc0 = W + n0 + tid;                   // thread = W column
    __half* adst = As + tid * AST;
    __half* bdst = Bs + tid * AST;

    float4 ra[8];
    float wr[32];
    #pragma unroll
    for (int j = 0; j < 8; j++) ra[j] = *(const float4*)(asrc0 + 4 * j);
    #pragma unroll
    for (int k = 0; k < 32; k++) wr[k] = wsrc0[(size_t)k * DMODEL];

    float c[4][8][4];
    #pragma unroll
    for (int mt = 0; mt < 4; mt++)
        #pragma unroll
        for (int nt = 0; nt < 8; nt++)
            #pragma unroll
            for (int i = 0; i < 4; i++) c[mt][nt][i] = 0.0f;

    for (int t = 0; t < 16; t++) {
        __syncthreads();   // previous compute done before overwriting smem
        {
            // fp16 convert + perm16 repack (pure register work), then 4 STS.128 each
            __half ha[32], hb[32];
            const float* rf = (const float*)ra;
            #pragma unroll
            for (int k = 0; k < 32; k++) {
                ha[(k & ~15) | PRM16(k & 15)] = __float2half_rn(rf[k]);
                hb[(k & ~15) | PRM16(k & 15)] = __float2half_rn(wr[k]);
            }
            #pragma unroll
            for (int j = 0; j < 4; j++) {
                *(uint4*)(adst + 8 * j) = *(const uint4*)(ha + 8 * j);
                *(uint4*)(bdst + 8 * j) = *(const uint4*)(hb + 8 * j);
            }
        }
        __syncthreads();

        if (t + 1 < 16) {  // prefetch next chunk; LDG latency overlaps compute
            const float* an = asrc0 + (t + 1) * 32;
            const float* wn_ = wsrc0 + (size_t)(t + 1) * 32 * DMODEL;
            #pragma unroll
            for (int j = 0; j < 8; j++) ra[j] = *(const float4*)(an + 4 * j);
            #pragma unroll
            for (int k = 0; k < 32; k++) wr[k] = wn_[(size_t)k * DMODEL];
        }

        #pragma unroll
        for (int ks = 0; ks < 2; ks++) {
            uint32_t A[4][4];
            #pragma unroll
            for (int mt = 0; mt < 4; mt++) {
                const __half* ap = As + (wm + mt * 16 + (lane >> 2)) * AST + 16 * ks + 4 * (lane & 3);
                uint2 lo = *(const uint2*)ap;
                uint2 hi = *(const uint2*)(ap + 8 * AST);
                A[mt][0] = lo.x; A[mt][1] = hi.x;
                A[mt][2] = lo.y; A[mt][3] = hi.y;
            }
            #pragma unroll
            for (int nt = 0; nt < 8; nt++) {
                const __half* bp = Bs + (wn + 8 * nt + (lane >> 2)) * AST + 16 * ks + 4 * (lane & 3);
                uint2 bb = *(const uint2*)bp;
                #pragma unroll
                for (int mt = 0; mt < 4; mt++) mma16(c[mt][nt], A[mt], bb.x, bb.y);
            }
        }
    }

    // Epilogue: bias + fp16 round + perm16 layout scatter (same as R13)
    #pragma unroll
    for (int mt = 0; mt < 4; mt++) {
        #pragma unroll
        for (int nt = 0; nt < 8; nt++) {
            const int d = n0 + wn + 8 * nt + 2 * (lane & 3);
            const float2 bb = *(const float2*)&bias[d];
            const int head = d >> 6;
            const int dh = d & 63;                       // even
            const int pq = (dh & ~15) | PRM16(dh & 15);  // pair -> (pq, pq+1)
            #pragma unroll
            for (int rh = 0; rh < 2; rh++) {
                const int m = m0 + wm + 16 * mt + (lane >> 2) + 8 * rh;
                float v0 = c[mt][nt][2 * rh] + bb.x;
                float v1 = c[mt][nt][2 * rh + 1] + bb.y;
                if (z == 0) { v0 *= QSCALE; v1 *= QSCALE; }
                const __half h0 = __float2half_rn(v0);
                const __half h1 = __float2half_rn(v1);
                if (z == 2) {
                    const int b = m >> 10, s = m & 1023;
                    const int ps = (s & ~15) | PRM16(s & 15);
                    __half* base = Out + (size_t)head * HSTRIDE + (size_t)b * (SEQ * HD) + ps;
                    base[(size_t)dh * SEQ]       = h0;
                    base[(size_t)(dh + 1) * SEQ] = h1;
                } else {
                    __half* base = Out + (size_t)head * HSTRIDE + (size_t)m * HD + pq;
                    *(__half2*)base = __halves2half2(h0, h1);
                }
            }
        }
    }
}

// ---------------------------------------------------------------------------
// Kernel B: flash attention, fp16 MMA (R13 — best measured, unchanged).
// ---------------------------------------------------------------------------
#define KSTRh 80
#define VSTRh 48

__global__ void __launch_bounds__(128, 2) attn_kernel(float* __restrict__ out)
{
    __shared__ __half Ks[2][32 * KSTRh];   // 10240 B
    __shared__ __half Vs[2][64 * VSTRh];   // 12288 B

    const int n = blockIdx.y;
    const int tid = threadIdx.x;
    const int lane = tid & 31, warp = tid >> 5;
    const int q0 = blockIdx.x * 128;

    const __half* Kg = g_K + (size_t)n * SEQ * HD;
    const __half* Vg = g_V + (size_t)n * SEQ * HD;   // [64][1024]

    uint32_t qA[2][4][4];
    {
        #pragma unroll
        for (int mt = 0; mt < 2; mt++) {
            const int row = q0 + warp * 32 + mt * 16 + (lane >> 2);
            const __half* rp = g_Q + ((size_t)n * SEQ + row) * HD;
            #pragma unroll
            for (int ks = 0; ks < 4; ks++) {
                uint2 lo = *(const uint2*)(rp + 16 * ks + 4 * (lane & 3));
                uint2 hi = *(const uint2*)(rp + 8 * HD + 16 * ks + 4 * (lane & 3));
                qA[mt][ks][0] = lo.x; qA[mt][ks][1] = hi.x;
                qA[mt][ks][2] = lo.y; qA[mt][ks][3] = hi.y;
            }
        }
    }

    float o[2][8][4];
    #pragma unroll
    for (int mt = 0; mt < 2; mt++)
        #pragma unroll
        for (int nt = 0; nt < 8; nt++)
            #pragma unroll
            for (int i = 0; i < 4; i++) o[mt][nt][i] = 0.0f;
    float lrow[4] = {0.0f, 0.0f, 0.0f, 0.0f};

    const int krow = tid >> 2, kc = tid & 3;
    const int vrow = tid >> 1, vc = tid & 1;
    const uint32_t ks_a = (uint32_t)__cvta_generic_to_shared(&Ks[0][0]);
    const uint32_t vs_a = (uint32_t)__cvta_generic_to_shared(&Vs[0][0]);

    #define ISSUE_TILE(kv, b) do {                                                 \
        uint32_t kd = ks_a + (uint32_t)(((b) * 32 * KSTRh + krow * KSTRh) * 2 + kc * 32); \
        const __half* ksrc = Kg + (size_t)((kv) + krow) * HD + kc * 16;            \
        cpa16(kd, ksrc); cpa16(kd + 16, ksrc + 8);                                 \
        uint32_t vd = vs_a + (uint32_t)(((b) * 64 * VSTRh + vrow * VSTRh) * 2 + vc * 32); \
        const __half* vsrc = Vg + (size_t)vrow * SEQ + (kv) + vc * 16;             \
        cpa16(vd, vsrc); cpa16(vd + 16, vsrc + 8);                                 \
        asm volatile("cp.async.commit_group;\n" ::: "memory");                     \
    } while (0)

    ISSUE_TILE(0, 0);

    for (int t = 0; t < 32; t++) {
        if (t + 1 < 32) {
            ISSUE_TILE((t + 1) * 32, (t + 1) & 1);
            asm volatile("cp.async.wait_group 1;\n" ::: "memory");
        } else {
            asm volatile("cp.async.wait_group 0;\n" ::: "memory");
        }
        __syncthreads();
        const __half* Kb = &Ks[t & 1][0];
        const __half* Vb = &Vs[t & 1][0];

        float s[2][4][4];
        #pragma unroll
        for (int mt = 0; mt < 2; mt++)
            #pragma unroll
            for (int nt = 0; nt < 4; nt++)
                #pragma unroll
                for (int i = 0; i < 4; i++) s[mt][nt][i] = 0.0f;

        #pragma unroll
        for (int ks = 0; ks < 4; ks++) {
            #pragma unroll
            for (int nt = 0; nt < 4; nt++) {
                uint2 kv2 = *(const uint2*)&Kb[(8 * nt + (lane >> 2)) * KSTRh + 16 * ks + 4 * (lane & 3)];
                mma16(s[0][nt], qA[0][ks], kv2.x, kv2.y);
                mma16(s[1][nt], qA[1][ks], kv2.x, kv2.y);
            }
        }

        #pragma unroll
        for (int mt = 0; mt < 2; mt++)
            #pragma unroll
            for (int nt = 0; nt < 4; nt++) {
                float p0 = ex2(s[mt][nt][0]);
                float p1 = ex2(s[mt][nt][1]);
                float p2 = ex2(s[mt][nt][2]);
                float p3 = ex2(s[mt][nt][3]);
                s[mt][nt][0] = p0; s[mt][nt][1] = p1;
                s[mt][nt][2] = p2; s[mt][nt][3] = p3;
                lrow[mt * 2 + 0] += p0 + p1;
                lrow[mt * 2 + 1] += p2 + p3;
            }

        uint32_t pA[2][2][4];
        #pragma unroll
        for (int mt = 0; mt < 2; mt++)
            #pragma unroll
            for (int kt = 0; kt < 2; kt++) {
                pA[mt][kt][0] = packh(s[mt][2 * kt][1],     s[mt][2 * kt][0]);
                pA[mt][kt][1] = packh(s[mt][2 * kt][3],     s[mt][2 * kt][2]);
                pA[mt][kt][2] = packh(s[mt][2 * kt + 1][1], s[mt][2 * kt + 1][0]);
                pA[mt][kt][3] = packh(s[mt][2 * kt + 1][3], s[mt][2 * kt + 1][2]);
            }

        #pragma unroll
        for (int kt = 0; kt < 2; kt++) {
            #pragma unroll
            for (int nt = 0; nt < 8; nt++) {
                uint2 vv = *(const uint2*)&Vb[(8 * nt + (lane >> 2)) * VSTRh + 16 * kt + 4 * (lane & 3)];
                mma16(o[0][nt], pA[0][kt], vv.x, vv.y);
                mma16(o[1][nt], pA[1][kt], vv.x, vv.y);
            }
        }
        __syncthreads();
    }
    #undef ISSUE_TILE

    const int head = n >> 3, b = n & 7;
    #pragma unroll
    for (int sl = 0; sl < 4; sl++) {
        lrow[sl] += __shfl_xor_sync(0xffffffffu, lrow[sl], 1);
        lrow[sl] += __shfl_xor_sync(0xffffffffu, lrow[sl], 2);
    }
    #pragma unroll
    for (int mt = 0; mt < 2; mt++) {
        #pragma unroll
        for (int rh = 0; rh < 2; rh++) {
            const int q = q0 + warp * 32 + mt * 16 + (lane >> 2) + 8 * rh;
            const float inv = 1.0f / lrow[mt * 2 + rh];
            float* orow = out + ((size_t)(b * SEQ + q)) * DMODEL + head * HD;
            #pragma unroll
            for (int nt = 0; nt < 8; nt++) {
                const int cc = 8 * nt + 2 * (lane & 3);
                *(float2*)(orow + cc) =
                    make_float2(o[mt][nt][2 * rh] * inv, o[mt][nt][2 * rh + 1] * inv);
            }
        }
    }
}

extern "C" void kernel_launch(void* const* d_in, const int* in_sizes, int n_in,
                              void* d_out, int out_size)
{
    const float* q_in = (const float*)d_in[0];
    const float* k_in = (const float*)d_in[1];
    const float* v_in = (const float*)d_in[2];
    const float* Wq   = (const float*)d_in[3];
    const float* bq   = (const float*)d_in[4];
    const float* Wk   = (const float*)d_in[5];
    const float* bk   = (const float*)d_in[6];
    const float* Wv   = (const float*)d_in[7];
    const float* bv   = (const float*)d_in[8];
    float* out = (float*)d_out;

    dim3 gp(DMODEL / 128, (BATCH * SEQ) / 128, 3);   // (4, 64, 3)
    proj_kernel<<<gp, 128>>>(q_in, k_in, v_in, Wq, Wk, Wv, bq, bk, bv);

    dim3 ga(SEQ / 128, NB);                          // (8, 64)
    attn_kernel<<<ga, 128>>>(out);
}